// round 7
// baseline (speedup 1.0000x reference)
#include <cuda_runtime.h>
#include <cstddef>
#include <cstdint>

// KPN per-pixel dynamic convolution, K=15.
// data:    [1, 8, 3, 96, 96]      float32
// kernels: [1, 8, 225, 3, 96, 96] float32   (tap-major: k = i*15 + j)
// out:     [1, 8, 3, 96, 96]      float32
//
// R7 = R6 with the prologue reordered: cp.async pipe-fill issues BEFORE the
// data-tile load, so the 200 MB kernels stream starts at block entry and the
// tile-load latency (previously ~5K dead cycles per block, all blocks
// simultaneously) hides under it. Tile load unrolled for MLP.

#define KSZ    15
#define PAD    7
#define HH     96
#define WW     96
#define CCH    3
#define TTT    8
#define TILE_H 4
#define SMEM_W 112                 // 96 + 14 halo -> 112
#define SMEM_H (TILE_H + KSZ - 1)  // 18
#define SLAB   (HH * WW)           // 9216
#define KSTRIDE (CCH * HH * WW)    // 27648 floats between consecutive taps
#define NTH    96                  // 24 x 4 threads
#define GSIZE  5                   // taps per async group
#define NGROUPS 45                 // 225 taps / 5
#define PIPE   5                   // groups in flight
#define SLOTS  (PIPE * GSIZE)      // 25 ring slots per thread

__global__ __launch_bounds__(NTH)
void kpn_kernel(const float* __restrict__ data,
                const float* __restrict__ kernels,
                float* __restrict__ out)
{
    __shared__ float  tile[SMEM_H * SMEM_W];     // 8064 B
    __shared__ float4 ring[SLOTS * NTH];         // 38400 B (46464 total < 48K)

    const int tc = blockIdx.y;             // t*3 + c, 0..23
    const int h0 = blockIdx.x * TILE_H;
    const int tx = threadIdx.x;            // 0..23  (w/4)
    const int ty = threadIdx.y;            // 0..3
    const int tid = ty * 24 + tx;          // 0..95

    const int w = tx * 4;
    const int h = h0 + ty;
    const int t = tc / CCH;
    const int c = tc - t * CCH;

    // kernels[t, k, c, h, w], tap k strides by KSTRIDE (16B-aligned: w%4==0)
    const float* kbase = kernels
        + ((size_t)(t * (KSZ * KSZ)) * CCH + c) * SLAB
        + (size_t)h * WW + w;

    const uint32_t ring_base =
        (uint32_t)__cvta_generic_to_shared(&ring[tid]);

    // Issue async group gg (5 taps, 16B each); always commit (empty groups
    // past the end keep the wait_group arithmetic uniform).
    auto issue = [&](int gg) {
        if (gg < NGROUPS) {
            const int slotg = gg % PIPE;
            #pragma unroll
            for (int u = 0; u < GSIZE; u++) {
                const int k = gg * GSIZE + u;
                const uint32_t dst =
                    ring_base + (uint32_t)((slotg * GSIZE + u) * NTH) * 16u;
                const float* src = kbase + (size_t)k * KSTRIDE;
                asm volatile("cp.async.cg.shared.global [%0], [%1], 16;\n"
                             :: "r"(dst), "l"(src) : "memory");
            }
        }
        asm volatile("cp.async.commit_group;\n" ::: "memory");
    };

    // ---- FIRST: fill the async pipe (25 taps outstanding) so the HBM
    // stream starts immediately at block entry ----
    #pragma unroll
    for (int g = 0; g < PIPE; g++) issue(g);

    // ---- THEN: cooperative load of padded data tile (hides under stream) ----
    const float* dslab = data + (size_t)tc * SLAB;
    #pragma unroll
    for (int v = 0; v < (SMEM_H * SMEM_W + NTH - 1) / NTH; v++) {
        const int idx = v * NTH + tid;
        if (idx < SMEM_H * SMEM_W) {
            const int r  = idx / SMEM_W;
            const int cc = idx - r * SMEM_W;
            const int gh = h0 - PAD + r;
            const int gw = cc - PAD;
            float val = 0.0f;
            if ((unsigned)gh < (unsigned)HH && (unsigned)gw < (unsigned)WW)
                val = __ldg(dslab + gh * WW + gw);
            tile[idx] = val;
        }
    }
    __syncthreads();

    float acc0 = 0.0f, acc1 = 0.0f, acc2 = 0.0f, acc3 = 0.0f;

    #pragma unroll 3
    for (int i = 0; i < KSZ; i++) {
        // data row segment: smem cols w .. w+19 (taps j=0..14 for 4 outputs)
        const float* rowp = &tile[(ty + i) * SMEM_W + w];
        float d[20];
        #pragma unroll
        for (int v4 = 0; v4 < 5; v4++) {
            const float4 rv = *reinterpret_cast<const float4*>(rowp + v4 * 4);
            d[v4 * 4 + 0] = rv.x;
            d[v4 * 4 + 1] = rv.y;
            d[v4 * 4 + 2] = rv.z;
            d[v4 * 4 + 3] = rv.w;
        }
        #pragma unroll
        for (int b = 0; b < 3; b++) {
            const int g = i * 3 + b;
            // oldest group (g) must be complete; 4 newer groups may be pending
            asm volatile("cp.async.wait_group 4;\n" ::: "memory");
            const int slotg = g % PIPE;
            #pragma unroll
            for (int u = 0; u < GSIZE; u++) {
                const float4 kv = ring[(slotg * GSIZE + u) * NTH + tid];
                const int j = b * GSIZE + u;
                acc0 = fmaf(kv.x, d[j + 0], acc0);
                acc1 = fmaf(kv.y, d[j + 1], acc1);
                acc2 = fmaf(kv.z, d[j + 2], acc2);
                acc3 = fmaf(kv.w, d[j + 3], acc3);
            }
            issue(g + PIPE);
        }
    }

    *reinterpret_cast<float4*>(out + (size_t)tc * SLAB + (size_t)h * WW + w)
        = make_float4(acc0, acc1, acc2, acc3);
}

extern "C" void kernel_launch(void* const* d_in, const int* in_sizes, int n_in,
                              void* d_out, int out_size)
{
    // data is the small tensor (221184), kernels the big one (49766400);
    // detect by size to be robust to metadata ordering.
    const float* data;
    const float* kernels;
    if (in_sizes[0] < in_sizes[1]) {
        data    = (const float*)d_in[0];
        kernels = (const float*)d_in[1];
    } else {
        data    = (const float*)d_in[1];
        kernels = (const float*)d_in[0];
    }

    dim3 grid(HH / TILE_H, TTT * CCH);   // (24, 24) = 576 blocks, one wave
    dim3 block(24, TILE_H);              // 96 threads, 4 px/thread
    kpn_kernel<<<grid, block>>>(data, kernels, (float*)d_out);
}